// round 12
// baseline (speedup 1.0000x reference)
#include <cuda_runtime.h>
#include <math.h>

#define MM 4096
#define DD 2048
#define INV_SQRT_M 0.015625f   // 1/sqrt(4096) exact

// ---------------- device scratch ----------------
__device__ float g_qt[MM];
__device__ float g_k[MM];
__device__ float g_v[MM];
__device__ float g_it, g_ft, g_ot;
__device__ float g_kqt, g_denom;
__device__ float g_pcp[MM][8];      // (row, chunk) cp@qt partials
__device__ int   g_cnt[MM];         // per-row arrival counters (self-resetting)

__device__ __forceinline__ float dot4(float4 a, float4 b) {
    return a.x * b.x + a.y * b.y + a.z * b.z + a.w * b.w;
}

// ---------------- kernel 1: fused q/k/v matvecs + gates (round-6: 19.7us) ----------------
// grid = MM+1 blocks x 256 threads; block b < MM computes row b of Wq/Wk/Wv,
// block MM computes the three gates. 6 front-batched streaming loads/thread.
__global__ __launch_bounds__(256) void mv_kernel(
    const float* __restrict__ x,
    const float* __restrict__ Wq, const float* __restrict__ bq,
    const float* __restrict__ Wk, const float* __restrict__ bk,
    const float* __restrict__ Wv, const float* __restrict__ bV,
    const float* __restrict__ Wi, const float* __restrict__ bi,
    const float* __restrict__ Wf, const float* __restrict__ bf,
    const float* __restrict__ Wo, const float* __restrict__ bo)
{
    const int b = blockIdx.x;
    const int t = threadIdx.x;

    const bool gate = (b == MM);
    const float *rA, *rB, *rC;
    if (!gate) {
        rA = Wq + (size_t)b * DD;
        rB = Wk + (size_t)b * DD;
        rC = Wv + (size_t)b * DD;
    } else {
        rA = Wi; rB = Wf; rC = Wo;
    }

    const float4* A4 = reinterpret_cast<const float4*>(rA);
    const float4* B4 = reinterpret_cast<const float4*>(rB);
    const float4* C4 = reinterpret_cast<const float4*>(rC);
    const float4* x4 = reinterpret_cast<const float4*>(x);

    // 6 independent streaming loads, front-batched (MLP=6)
    float4 a0 = __ldcs(&A4[t]);
    float4 a1 = __ldcs(&A4[t + 256]);
    float4 k0 = __ldcs(&B4[t]);
    float4 k1 = __ldcs(&B4[t + 256]);
    float4 v0 = __ldcs(&C4[t]);
    float4 v1 = __ldcs(&C4[t + 256]);
    float4 x0 = x4[t];
    float4 x1 = x4[t + 256];

    float sa = dot4(a0, x0) + dot4(a1, x1);
    float sk = dot4(k0, x0) + dot4(k1, x1);
    float sv = dot4(v0, x0) + dot4(v1, x1);

    #pragma unroll
    for (int o = 16; o > 0; o >>= 1) {
        sa += __shfl_down_sync(0xFFFFFFFFu, sa, o);
        sk += __shfl_down_sync(0xFFFFFFFFu, sk, o);
        sv += __shfl_down_sync(0xFFFFFFFFu, sv, o);
    }

    __shared__ float wsa[8], wsk[8], wsv[8];
    if ((t & 31) == 0) {
        const int w = t >> 5;
        wsa[w] = sa; wsk[w] = sk; wsv[w] = sv;
    }
    __syncthreads();
    if (t < 8) {
        float ra = wsa[t], rk = wsk[t], rv = wsv[t];
        #pragma unroll
        for (int o = 4; o > 0; o >>= 1) {
            ra += __shfl_down_sync(0xFFu, ra, o, 8);
            rk += __shfl_down_sync(0xFFu, rk, o, 8);
            rv += __shfl_down_sync(0xFFu, rv, o, 8);
        }
        if (t == 0) {
            if (!gate) {
                g_qt[b] = ra + bq[b];
                g_k[b]  = INV_SQRT_M * (rk + bk[b]);
                g_v[b]  = rv + bV[b];
            } else {
                g_it = expf(ra + bi[0]);
                g_ft = expf(rk + bf[0]);
                float z = rv + bo[0];
                g_ot = 1.0f / (1.0f + expf(-z));
            }
        }
    }
}

// ---------------- kernel 2: n-update + kqt/denom ----------------
__global__ __launch_bounds__(1024) void nred_kernel(
    const float* __restrict__ n_prev, float* __restrict__ out_n)
{
    const int t = threadIdx.x;
    const float ft = g_ft, it = g_it;
    __shared__ float red[2][32];

    float kqt = 0.f, nqt = 0.f;
    #pragma unroll
    for (int u = 0; u < MM / 1024; u++) {
        const int i = t + u * 1024;
        const float k = g_k[i];
        const float q = g_qt[i];
        kqt += k * q;
        const float n = ft * n_prev[i] + it * k;
        out_n[i] = n;
        nqt += n * q;
    }
    #pragma unroll
    for (int o = 16; o > 0; o >>= 1) {
        kqt += __shfl_down_sync(0xFFFFFFFFu, kqt, o);
        nqt += __shfl_down_sync(0xFFFFFFFFu, nqt, o);
    }
    if ((t & 31) == 0) { red[0][t >> 5] = kqt; red[1][t >> 5] = nqt; }
    __syncthreads();
    if (t < 32) {
        float a = red[0][t], bb = red[1][t];
        #pragma unroll
        for (int o = 16; o > 0; o >>= 1) {
            a  += __shfl_down_sync(0xFFFFFFFFu, a, o);
            bb += __shfl_down_sync(0xFFFFFFFFu, bb, o);
        }
        if (t == 0) {
            g_kqt = a;
            g_denom = fmaxf(fabsf(bb), 1.0f);
        }
    }
}

// ---------------- kernel 3: sync-free cp stream + fused ht fold ----------------
// One warp owns one 512-float chunk of one cp row: elementwise C write +
// warp-shuffle partial of cp@qt. Last-arriving warp per row (atomic counter)
// sums the 8 partials in fixed order (deterministic) and writes ht[row],
// then resets the counter for the next graph replay.
__global__ __launch_bounds__(256) void cp_partial(
    const float* __restrict__ cp, float* __restrict__ outC,
    float* __restrict__ outH)
{
    const int w    = blockIdx.x * 8 + (threadIdx.x >> 5);
    const int lane = threadIdx.x & 31;
    const int row  = w >> 3;
    const int ch   = w & 7;

    const float ft = g_ft;
    const float iv = g_it * g_v[row];

    const size_t base = (size_t)row * MM + ch * 512;
    const float4* P  = reinterpret_cast<const float4*>(cp + base);
    float4*       O  = reinterpret_cast<float4*>(outC + base);
    const float4* k4 = reinterpret_cast<const float4*>(g_k + ch * 512);
    const float4* q4 = reinterpret_cast<const float4*>(g_qt + ch * 512);

    // 4 independent streaming loads front-batched
    float4 c0 = __ldcs(&P[lane]);
    float4 c1 = __ldcs(&P[lane + 32]);
    float4 c2 = __ldcs(&P[lane + 64]);
    float4 c3 = __ldcs(&P[lane + 96]);
    float4 k0 = k4[lane], k1 = k4[lane + 32], k2 = k4[lane + 64], k3 = k4[lane + 96];
    float4 q0 = q4[lane], q1 = q4[lane + 32], q2 = q4[lane + 64], q3 = q4[lane + 96];

    float4 o;
    o.x = ft * c0.x + iv * k0.x; o.y = ft * c0.y + iv * k0.y;
    o.z = ft * c0.z + iv * k0.z; o.w = ft * c0.w + iv * k0.w;
    __stcs(&O[lane], o);
    o.x = ft * c1.x + iv * k1.x; o.y = ft * c1.y + iv * k1.y;
    o.z = ft * c1.z + iv * k1.z; o.w = ft * c1.w + iv * k1.w;
    __stcs(&O[lane + 32], o);
    o.x = ft * c2.x + iv * k2.x; o.y = ft * c2.y + iv * k2.y;
    o.z = ft * c2.z + iv * k2.z; o.w = ft * c2.w + iv * k2.w;
    __stcs(&O[lane + 64], o);
    o.x = ft * c3.x + iv * k3.x; o.y = ft * c3.y + iv * k3.y;
    o.z = ft * c3.z + iv * k3.z; o.w = ft * c3.w + iv * k3.w;
    __stcs(&O[lane + 96], o);

    float s = dot4(c0, q0) + dot4(c1, q1) + dot4(c2, q2) + dot4(c3, q3);
    #pragma unroll
    for (int o2 = 16; o2 > 0; o2 >>= 1) s += __shfl_down_sync(0xFFFFFFFFu, s, o2);

    if (lane == 0) {
        g_pcp[row][ch] = s;
        __threadfence();                       // partial visible before arrival
        const int old = atomicAdd(&g_cnt[row], 1);
        if (old == 7) {
            // last arrival: fold in fixed order (deterministic), write ht
            float acc = 0.f;
            #pragma unroll
            for (int c = 0; c < 8; c++) acc += __ldcg(&g_pcp[row][c]);
            outH[row] = (g_ot / g_denom) * (ft * acc + iv * g_kqt);
            g_cnt[row] = 0;                    // reset for next replay
        }
    }
}

// ---------------- launch ----------------
extern "C" void kernel_launch(void* const* d_in, const int* in_sizes, int n_in,
                              void* d_out, int out_size)
{
    const float* x      = (const float*)d_in[0];
    const float* cp     = (const float*)d_in[1];
    const float* n_prev = (const float*)d_in[2];
    const float* Wq     = (const float*)d_in[3];
    const float* bq     = (const float*)d_in[4];
    const float* Wk     = (const float*)d_in[5];
    const float* bk     = (const float*)d_in[6];
    const float* Wv     = (const float*)d_in[7];
    const float* bV     = (const float*)d_in[8];
    const float* Wi     = (const float*)d_in[9];
    const float* bi     = (const float*)d_in[10];
    const float* Wf     = (const float*)d_in[11];
    const float* bf     = (const float*)d_in[12];
    const float* Wo     = (const float*)d_in[13];
    const float* bo     = (const float*)d_in[14];

    float* out  = (float*)d_out;
    float* outH = out;                        // ht: M
    float* outC = out + MM;                   // C : M*M
    float* outN = out + MM + (size_t)MM * MM; // n : M

    mv_kernel<<<MM + 1, 256>>>(x, Wq, bq, Wk, bk, Wv, bV,
                               Wi, bi, Wf, bf, Wo, bo);
    nred_kernel<<<1, 1024>>>(n_prev, outN);
    cp_partial<<<4096, 256>>>(cp, outC, outH);
}

// round 13
// speedup vs baseline: 1.0535x; 1.0535x over previous
#include <cuda_runtime.h>
#include <math.h>

#define MM 4096
#define DD 2048
#define INV_SQRT_M 0.015625f   // 1/sqrt(4096) exact

// ---------------- device scratch ----------------
__device__ float g_qt[MM];
__device__ float g_k[MM];
__device__ float g_v[MM];
__device__ float g_it, g_ft, g_ot;
__device__ float g_kqt, g_denom;
__device__ float g_pmv[3][MM][4];   // (matrix, row, chunk) matvec partials
__device__ float g_pcp[MM][8];      // (row, chunk) cp@qt partials

__device__ __forceinline__ float dot4(float4 a, float4 b) {
    return a.x * b.x + a.y * b.y + a.z * b.z + a.w * b.w;
}

// ---------------- kernel 1: sync-free matvec partials, x amortized ----------------
// One warp owns chunk ch (512 floats) of row `row` for ALL THREE matrices:
// 4 x loads (L2-cached) amortized over 12 streaming W loads (MLP=12).
// 3 warp-shuffle dots, 3 scalar partial stores. No smem, no syncthreads.
// 16384 warps = 2048 blocks x 256 threads.
__global__ __launch_bounds__(256) void mv_partial2(
    const float* __restrict__ x,
    const float* __restrict__ Wq,
    const float* __restrict__ Wk,
    const float* __restrict__ Wv)
{
    const int w    = blockIdx.x * 8 + (threadIdx.x >> 5);
    const int lane = threadIdx.x & 31;
    const int row  = w >> 2;
    const int ch   = w & 3;

    const size_t off = (size_t)row * DD + ch * 512;
    const float4* Q4 = reinterpret_cast<const float4*>(Wq + off);
    const float4* K4 = reinterpret_cast<const float4*>(Wk + off);
    const float4* V4 = reinterpret_cast<const float4*>(Wv + off);
    const float4* x4 = reinterpret_cast<const float4*>(x + ch * 512);

    // 12 independent streaming loads front-batched (MLP=12)
    float4 q0 = __ldcs(&Q4[lane]);
    float4 q1 = __ldcs(&Q4[lane + 32]);
    float4 q2 = __ldcs(&Q4[lane + 64]);
    float4 q3 = __ldcs(&Q4[lane + 96]);
    float4 k0 = __ldcs(&K4[lane]);
    float4 k1 = __ldcs(&K4[lane + 32]);
    float4 k2 = __ldcs(&K4[lane + 64]);
    float4 k3 = __ldcs(&K4[lane + 96]);
    float4 v0 = __ldcs(&V4[lane]);
    float4 v1 = __ldcs(&V4[lane + 32]);
    float4 v2 = __ldcs(&V4[lane + 64]);
    float4 v3 = __ldcs(&V4[lane + 96]);
    float4 xa = x4[lane];
    float4 xb = x4[lane + 32];
    float4 xc = x4[lane + 64];
    float4 xd = x4[lane + 96];

    float sq = dot4(q0, xa) + dot4(q1, xb) + dot4(q2, xc) + dot4(q3, xd);
    float sk = dot4(k0, xa) + dot4(k1, xb) + dot4(k2, xc) + dot4(k3, xd);
    float sv = dot4(v0, xa) + dot4(v1, xb) + dot4(v2, xc) + dot4(v3, xd);

    #pragma unroll
    for (int o = 16; o > 0; o >>= 1) {
        sq += __shfl_down_sync(0xFFFFFFFFu, sq, o);
        sk += __shfl_down_sync(0xFFFFFFFFu, sk, o);
        sv += __shfl_down_sync(0xFFFFFFFFu, sv, o);
    }
    if (lane == 0) {
        g_pmv[0][row][ch] = sq;
        g_pmv[1][row][ch] = sk;
        g_pmv[2][row][ch] = sv;
    }
}

// ---------------- kernel 2: fold matvec partials -> qt, k, v ----------------
__global__ __launch_bounds__(512) void qkv_reduce(
    const float* __restrict__ bq,
    const float* __restrict__ bk,
    const float* __restrict__ bV)
{
    const int r = blockIdx.x * 512 + threadIdx.x;
    const float4 pq = *reinterpret_cast<const float4*>(g_pmv[0][r]);
    const float4 pk = *reinterpret_cast<const float4*>(g_pmv[1][r]);
    const float4 pv = *reinterpret_cast<const float4*>(g_pmv[2][r]);
    g_qt[r] = (pq.x + pq.y) + (pq.z + pq.w) + bq[r];
    g_k[r]  = INV_SQRT_M * ((pk.x + pk.y) + (pk.z + pk.w) + bk[r]);
    g_v[r]  = (pv.x + pv.y) + (pv.z + pv.w) + bV[r];
}

// ---------------- kernel 3: gates + n-update + tiny reductions ----------------
__global__ __launch_bounds__(1024) void nred_kernel(
    const float* __restrict__ x,
    const float* __restrict__ Wi, const float* __restrict__ bi,
    const float* __restrict__ Wf, const float* __restrict__ bf,
    const float* __restrict__ Wo, const float* __restrict__ bo,
    const float* __restrict__ n_prev, float* __restrict__ out_n)
{
    const int t = threadIdx.x;
    __shared__ float red[3][32];
    __shared__ float gates[2];

    float si = 0.f, sf = 0.f, so = 0.f;
    #pragma unroll
    for (int u = 0; u < 2; u++) {
        const int i = t + u * 1024;
        const float xv = x[i];
        si += Wi[i] * xv;
        sf += Wf[i] * xv;
        so += Wo[i] * xv;
    }
    #pragma unroll
    for (int o = 16; o > 0; o >>= 1) {
        si += __shfl_down_sync(0xFFFFFFFFu, si, o);
        sf += __shfl_down_sync(0xFFFFFFFFu, sf, o);
        so += __shfl_down_sync(0xFFFFFFFFu, so, o);
    }
    if ((t & 31) == 0) {
        const int w = t >> 5;
        red[0][w] = si; red[1][w] = sf; red[2][w] = so;
    }
    __syncthreads();
    if (t < 32) {
        float a = red[0][t], bb = red[1][t], c = red[2][t];
        #pragma unroll
        for (int o = 16; o > 0; o >>= 1) {
            a  += __shfl_down_sync(0xFFFFFFFFu, a, o);
            bb += __shfl_down_sync(0xFFFFFFFFu, bb, o);
            c  += __shfl_down_sync(0xFFFFFFFFu, c, o);
        }
        if (t == 0) {
            const float itv = expf(a + bi[0]);
            const float ftv = expf(bb + bf[0]);
            const float z   = c + bo[0];
            g_it = itv; g_ft = ftv;
            g_ot = 1.0f / (1.0f + expf(-z));
            gates[0] = itv; gates[1] = ftv;
        }
    }
    __syncthreads();
    const float it = gates[0];
    const float ft = gates[1];

    float kqt = 0.f, nqt = 0.f;
    #pragma unroll
    for (int u = 0; u < MM / 1024; u++) {
        const int i = t + u * 1024;
        const float k = g_k[i];
        const float q = g_qt[i];
        kqt += k * q;
        const float n = ft * n_prev[i] + it * k;
        out_n[i] = n;
        nqt += n * q;
    }
    #pragma unroll
    for (int o = 16; o > 0; o >>= 1) {
        kqt += __shfl_down_sync(0xFFFFFFFFu, kqt, o);
        nqt += __shfl_down_sync(0xFFFFFFFFu, nqt, o);
    }
    __syncthreads();
    if ((t & 31) == 0) { red[0][t >> 5] = kqt; red[1][t >> 5] = nqt; }
    __syncthreads();
    if (t < 32) {
        float a = red[0][t], bb = red[1][t];
        #pragma unroll
        for (int o = 16; o > 0; o >>= 1) {
            a  += __shfl_down_sync(0xFFFFFFFFu, a, o);
            bb += __shfl_down_sync(0xFFFFFFFFu, bb, o);
        }
        if (t == 0) {
            g_kqt = a;
            g_denom = fmaxf(fabsf(bb), 1.0f);
        }
    }
}

// ---------------- kernel 4: sync-free cp stream + dot partials (20.3us) ----------------
__global__ __launch_bounds__(256) void cp_partial(
    const float* __restrict__ cp, float* __restrict__ outC)
{
    const int w    = blockIdx.x * 8 + (threadIdx.x >> 5);
    const int lane = threadIdx.x & 31;
    const int row  = w >> 3;
    const int ch   = w & 7;

    const float ft = g_ft;
    const float iv = g_it * g_v[row];

    const size_t base = (size_t)row * MM + ch * 512;
    const float4* P  = reinterpret_cast<const float4*>(cp + base);
    float4*       O  = reinterpret_cast<float4*>(outC + base);
    const float4* k4 = reinterpret_cast<const float4*>(g_k + ch * 512);
    const float4* q4 = reinterpret_cast<const float4*>(g_qt + ch * 512);

    // 4 independent streaming loads front-batched
    float4 c0 = __ldcs(&P[lane]);
    float4 c1 = __ldcs(&P[lane + 32]);
    float4 c2 = __ldcs(&P[lane + 64]);
    float4 c3 = __ldcs(&P[lane + 96]);
    float4 k0 = k4[lane], k1 = k4[lane + 32], k2 = k4[lane + 64], k3 = k4[lane + 96];
    float4 q0 = q4[lane], q1 = q4[lane + 32], q2 = q4[lane + 64], q3 = q4[lane + 96];

    float4 o;
    o.x = ft * c0.x + iv * k0.x; o.y = ft * c0.y + iv * k0.y;
    o.z = ft * c0.z + iv * k0.z; o.w = ft * c0.w + iv * k0.w;
    __stcs(&O[lane], o);
    o.x = ft * c1.x + iv * k1.x; o.y = ft * c1.y + iv * k1.y;
    o.z = ft * c1.z + iv * k1.z; o.w = ft * c1.w + iv * k1.w;
    __stcs(&O[lane + 32], o);
    o.x = ft * c2.x + iv * k2.x; o.y = ft * c2.y + iv * k2.y;
    o.z = ft * c2.z + iv * k2.z; o.w = ft * c2.w + iv * k2.w;
    __stcs(&O[lane + 64], o);
    o.x = ft * c3.x + iv * k3.x; o.y = ft * c3.y + iv * k3.y;
    o.z = ft * c3.z + iv * k3.z; o.w = ft * c3.w + iv * k3.w;
    __stcs(&O[lane + 96], o);

    float s = dot4(c0, q0) + dot4(c1, q1) + dot4(c2, q2) + dot4(c3, q3);
    #pragma unroll
    for (int o2 = 16; o2 > 0; o2 >>= 1) s += __shfl_down_sync(0xFFFFFFFFu, s, o2);
    if (lane == 0) g_pcp[row][ch] = s;
}

// ---------------- kernel 5: fold cp partials -> ht (latency-spread grid) ----------------
__global__ __launch_bounds__(128) void hred_kernel(float* __restrict__ outH)
{
    const int r = blockIdx.x * 128 + threadIdx.x;
    const float4 p0 = *reinterpret_cast<const float4*>(&g_pcp[r][0]);
    const float4 p1 = *reinterpret_cast<const float4*>(&g_pcp[r][4]);
    const float s = ((p0.x + p0.y) + (p0.z + p0.w))
                  + ((p1.x + p1.y) + (p1.z + p1.w));
    const float iv = g_it * g_v[r];
    outH[r] = (g_ot / g_denom) * (g_ft * s + iv * g_kqt);
}

// ---------------- launch ----------------
extern "C" void kernel_launch(void* const* d_in, const int* in_sizes, int n_in,
                              void* d_out, int out_size)
{
    const float* x      = (const float*)d_in[0];
    const float* cp     = (const float*)d_in[1];
    const float* n_prev = (const float*)d_in[2];
    const float* Wq     = (const float*)d_in[3];
    const float* bq     = (const float*)d_in[4];
    const float* Wk     = (const float*)d_in[5];
    const float* bk     = (const float*)d_in[6];
    const float* Wv     = (const float*)d_in[7];
    const float* bV     = (const float*)d_in[8];
    const float* Wi     = (const float*)d_in[9];
    const float* bi     = (const float*)d_in[10];
    const float* Wf     = (const float*)d_in[11];
    const float* bf     = (const float*)d_in[12];
    const float* Wo     = (const float*)d_in[13];
    const float* bo     = (const float*)d_in[14];

    float* out  = (float*)d_out;
    float* outH = out;                        // ht: M
    float* outC = out + MM;                   // C : M*M
    float* outN = out + MM + (size_t)MM * MM; // n : M

    mv_partial2<<<2048, 256>>>(x, Wq, Wk, Wv);
    qkv_reduce<<<MM / 512, 512>>>(bq, bk, bV);
    nred_kernel<<<1, 1024>>>(x, Wi, bi, Wf, bf, Wo, bo, n_prev, outN);
    cp_partial<<<4096, 256>>>(cp, outC);
    hred_kernel<<<MM / 128, 128>>>(outH);
}

// round 14
// speedup vs baseline: 1.1923x; 1.1318x over previous
#include <cuda_runtime.h>
#include <math.h>

#define MM 4096
#define DD 2048
#define INV_SQRT_M 0.015625f   // 1/sqrt(4096) exact

// ---------------- device scratch ----------------
__device__ float g_qt[MM];
__device__ float g_k[MM];
__device__ float g_v[MM];
__device__ float g_it, g_ft, g_ot;
__device__ float g_kqt, g_denom;

__device__ __forceinline__ float dot4(float4 a, float4 b) {
    return a.x * b.x + a.y * b.y + a.z * b.z + a.w * b.w;
}

// ---------------- kernel 1: fused q/k/v matvecs + gates (measured 19.7us) ----------------
// grid = MM+1 blocks x 256 threads; block b < MM computes row b of Wq/Wk/Wv,
// block MM computes the three gates. 6 front-batched streaming loads/thread.
__global__ __launch_bounds__(256) void mv_kernel(
    const float* __restrict__ x,
    const float* __restrict__ Wq, const float* __restrict__ bq,
    const float* __restrict__ Wk, const float* __restrict__ bk,
    const float* __restrict__ Wv, const float* __restrict__ bV,
    const float* __restrict__ Wi, const float* __restrict__ bi,
    const float* __restrict__ Wf, const float* __restrict__ bf,
    const float* __restrict__ Wo, const float* __restrict__ bo)
{
    const int b = blockIdx.x;
    const int t = threadIdx.x;

    const bool gate = (b == MM);
    const float *rA, *rB, *rC;
    if (!gate) {
        rA = Wq + (size_t)b * DD;
        rB = Wk + (size_t)b * DD;
        rC = Wv + (size_t)b * DD;
    } else {
        rA = Wi; rB = Wf; rC = Wo;
    }

    const float4* A4 = reinterpret_cast<const float4*>(rA);
    const float4* B4 = reinterpret_cast<const float4*>(rB);
    const float4* C4 = reinterpret_cast<const float4*>(rC);
    const float4* x4 = reinterpret_cast<const float4*>(x);

    // 6 independent streaming loads, front-batched (MLP=6)
    float4 a0 = __ldcs(&A4[t]);
    float4 a1 = __ldcs(&A4[t + 256]);
    float4 k0 = __ldcs(&B4[t]);
    float4 k1 = __ldcs(&B4[t + 256]);
    float4 v0 = __ldcs(&C4[t]);
    float4 v1 = __ldcs(&C4[t + 256]);
    float4 x0 = x4[t];
    float4 x1 = x4[t + 256];

    float sa = dot4(a0, x0) + dot4(a1, x1);
    float sk = dot4(k0, x0) + dot4(k1, x1);
    float sv = dot4(v0, x0) + dot4(v1, x1);

    #pragma unroll
    for (int o = 16; o > 0; o >>= 1) {
        sa += __shfl_down_sync(0xFFFFFFFFu, sa, o);
        sk += __shfl_down_sync(0xFFFFFFFFu, sk, o);
        sv += __shfl_down_sync(0xFFFFFFFFu, sv, o);
    }

    __shared__ float wsa[8], wsk[8], wsv[8];
    if ((t & 31) == 0) {
        const int w = t >> 5;
        wsa[w] = sa; wsk[w] = sk; wsv[w] = sv;
    }
    __syncthreads();
    if (t < 8) {
        float ra = wsa[t], rk = wsk[t], rv = wsv[t];
        #pragma unroll
        for (int o = 4; o > 0; o >>= 1) {
            ra += __shfl_down_sync(0xFFu, ra, o, 8);
            rk += __shfl_down_sync(0xFFu, rk, o, 8);
            rv += __shfl_down_sync(0xFFu, rv, o, 8);
        }
        if (t == 0) {
            if (!gate) {
                g_qt[b] = ra + bq[b];
                g_k[b]  = INV_SQRT_M * (rk + bk[b]);
                g_v[b]  = rv + bV[b];
            } else {
                g_it = expf(ra + bi[0]);
                g_ft = expf(rk + bf[0]);
                float z = rv + bo[0];
                g_ot = 1.0f / (1.0f + expf(-z));
            }
        }
    }
}

// ---------------- kernel 2: n-update + kqt/denom ----------------
__global__ __launch_bounds__(1024) void nred_kernel(
    const float* __restrict__ n_prev, float* __restrict__ out_n)
{
    const int t = threadIdx.x;
    const float ft = g_ft, it = g_it;
    __shared__ float red[2][32];

    float kqt = 0.f, nqt = 0.f;
    #pragma unroll
    for (int u = 0; u < MM / 1024; u++) {
        const int i = t + u * 1024;
        const float k = g_k[i];
        const float q = g_qt[i];
        kqt += k * q;
        const float n = ft * n_prev[i] + it * k;
        out_n[i] = n;
        nqt += n * q;
    }
    #pragma unroll
    for (int o = 16; o > 0; o >>= 1) {
        kqt += __shfl_down_sync(0xFFFFFFFFu, kqt, o);
        nqt += __shfl_down_sync(0xFFFFFFFFu, nqt, o);
    }
    if ((t & 31) == 0) { red[0][t >> 5] = kqt; red[1][t >> 5] = nqt; }
    __syncthreads();
    if (t < 32) {
        float a = red[0][t], bb = red[1][t];
        #pragma unroll
        for (int o = 16; o > 0; o >>= 1) {
            a  += __shfl_down_sync(0xFFFFFFFFu, a, o);
            bb += __shfl_down_sync(0xFFFFFFFFu, bb, o);
        }
        if (t == 0) {
            g_kqt = a;
            g_denom = fmaxf(fabsf(bb), 1.0f);
        }
    }
}

// ---------------- kernel 3: cp stream + in-block ht fold ----------------
// Identical streaming body to the measured-20.3us cp_partial: grid 4096,
// block 256; warp wi handles chunk wi of row blockIdx.x (4 front-batched
// streaming loads, elementwise C write, warp dot partial). The ONLY
// addition: partials go to smem and warp 0 folds them into ht[row] after a
// single __syncthreads() that executes after all loads/stores are issued.
__global__ __launch_bounds__(256) void cp_fused(
    const float* __restrict__ cp, float* __restrict__ outC,
    float* __restrict__ outH)
{
    const int row  = blockIdx.x;
    const int t    = threadIdx.x;
    const int ch   = t >> 5;
    const int lane = t & 31;

    const float ft = g_ft;
    const float iv = g_it * g_v[row];

    const size_t base = (size_t)row * MM + ch * 512;
    const float4* P  = reinterpret_cast<const float4*>(cp + base);
    float4*       O  = reinterpret_cast<float4*>(outC + base);
    const float4* k4 = reinterpret_cast<const float4*>(g_k + ch * 512);
    const float4* q4 = reinterpret_cast<const float4*>(g_qt + ch * 512);

    // 4 independent streaming loads front-batched
    float4 c0 = __ldcs(&P[lane]);
    float4 c1 = __ldcs(&P[lane + 32]);
    float4 c2 = __ldcs(&P[lane + 64]);
    float4 c3 = __ldcs(&P[lane + 96]);
    float4 k0 = k4[lane], k1 = k4[lane + 32], k2 = k4[lane + 64], k3 = k4[lane + 96];
    float4 q0 = q4[lane], q1 = q4[lane + 32], q2 = q4[lane + 64], q3 = q4[lane + 96];

    float4 o;
    o.x = ft * c0.x + iv * k0.x; o.y = ft * c0.y + iv * k0.y;
    o.z = ft * c0.z + iv * k0.z; o.w = ft * c0.w + iv * k0.w;
    __stcs(&O[lane], o);
    o.x = ft * c1.x + iv * k1.x; o.y = ft * c1.y + iv * k1.y;
    o.z = ft * c1.z + iv * k1.z; o.w = ft * c1.w + iv * k1.w;
    __stcs(&O[lane + 32], o);
    o.x = ft * c2.x + iv * k2.x; o.y = ft * c2.y + iv * k2.y;
    o.z = ft * c2.z + iv * k2.z; o.w = ft * c2.w + iv * k2.w;
    __stcs(&O[lane + 64], o);
    o.x = ft * c3.x + iv * k3.x; o.y = ft * c3.y + iv * k3.y;
    o.z = ft * c3.z + iv * k3.z; o.w = ft * c3.w + iv * k3.w;
    __stcs(&O[lane + 96], o);

    float s = dot4(c0, q0) + dot4(c1, q1) + dot4(c2, q2) + dot4(c3, q3);
    #pragma unroll
    for (int o2 = 16; o2 > 0; o2 >>= 1) s += __shfl_down_sync(0xFFFFFFFFu, s, o2);

    __shared__ float ws[8];
    if (lane == 0) ws[ch] = s;
    __syncthreads();
    if (t < 8) {
        float a = ws[t];
        #pragma unroll
        for (int o2 = 4; o2 > 0; o2 >>= 1) a += __shfl_down_sync(0xFFu, a, o2, 8);
        if (t == 0) outH[row] = (g_ot / g_denom) * (ft * a + iv * g_kqt);
    }
}

// ---------------- launch ----------------
extern "C" void kernel_launch(void* const* d_in, const int* in_sizes, int n_in,
                              void* d_out, int out_size)
{
    const float* x      = (const float*)d_in[0];
    const float* cp     = (const float*)d_in[1];
    const float* n_prev = (const float*)d_in[2];
    const float* Wq     = (const float*)d_in[3];
    const float* bq     = (const float*)d_in[4];
    const float* Wk     = (const float*)d_in[5];
    const float* bk     = (const float*)d_in[6];
    const float* Wv     = (const float*)d_in[7];
    const float* bV     = (const float*)d_in[8];
    const float* Wi     = (const float*)d_in[9];
    const float* bi     = (const float*)d_in[10];
    const float* Wf     = (const float*)d_in[11];
    const float* bf     = (const float*)d_in[12];
    const float* Wo     = (const float*)d_in[13];
    const float* bo     = (const float*)d_in[14];

    float* out  = (float*)d_out;
    float* outH = out;                        // ht: M
    float* outC = out + MM;                   // C : M*M
    float* outN = out + MM + (size_t)MM * MM; // n : M

    mv_kernel<<<MM + 1, 256>>>(x, Wq, bq, Wk, bk, Wv, bV,
                               Wi, bi, Wf, bf, Wo, bo);
    nred_kernel<<<1, 1024>>>(n_prev, outN);
    cp_fused<<<MM, 256>>>(cp, outC, outH);
}

// round 15
// speedup vs baseline: 1.2004x; 1.0068x over previous
#include <cuda_runtime.h>
#include <math.h>

#define MM 4096
#define DD 2048
#define INV_SQRT_M 0.015625f   // 1/sqrt(4096) exact

// ---------------- device scratch ----------------
__device__ float g_qt[MM];
__device__ float g_k[MM];
__device__ float g_v[MM];
__device__ float g_it, g_ft, g_ot;
__device__ float g_pcp[MM][8];      // (row, chunk) cp@qt partials

__device__ __forceinline__ float dot4(float4 a, float4 b) {
    return a.x * b.x + a.y * b.y + a.z * b.z + a.w * b.w;
}

// ---------------- kernel 1: fused q/k/v matvecs + gates (measured ~19.7us) ----------------
// grid = MM+1 blocks x 256 threads; block b < MM computes row b of Wq/Wk/Wv,
// block MM computes the three gates. 6 front-batched streaming loads/thread.
__global__ __launch_bounds__(256) void mv_kernel(
    const float* __restrict__ x,
    const float* __restrict__ Wq, const float* __restrict__ bq,
    const float* __restrict__ Wk, const float* __restrict__ bk,
    const float* __restrict__ Wv, const float* __restrict__ bV,
    const float* __restrict__ Wi, const float* __restrict__ bi,
    const float* __restrict__ Wf, const float* __restrict__ bf,
    const float* __restrict__ Wo, const float* __restrict__ bo)
{
    const int b = blockIdx.x;
    const int t = threadIdx.x;

    const bool gate = (b == MM);
    const float *rA, *rB, *rC;
    if (!gate) {
        rA = Wq + (size_t)b * DD;
        rB = Wk + (size_t)b * DD;
        rC = Wv + (size_t)b * DD;
    } else {
        rA = Wi; rB = Wf; rC = Wo;
    }

    const float4* A4 = reinterpret_cast<const float4*>(rA);
    const float4* B4 = reinterpret_cast<const float4*>(rB);
    const float4* C4 = reinterpret_cast<const float4*>(rC);
    const float4* x4 = reinterpret_cast<const float4*>(x);

    // 6 independent streaming loads, front-batched (MLP=6)
    float4 a0 = __ldcs(&A4[t]);
    float4 a1 = __ldcs(&A4[t + 256]);
    float4 k0 = __ldcs(&B4[t]);
    float4 k1 = __ldcs(&B4[t + 256]);
    float4 v0 = __ldcs(&C4[t]);
    float4 v1 = __ldcs(&C4[t + 256]);
    float4 x0 = x4[t];
    float4 x1 = x4[t + 256];

    float sa = dot4(a0, x0) + dot4(a1, x1);
    float sk = dot4(k0, x0) + dot4(k1, x1);
    float sv = dot4(v0, x0) + dot4(v1, x1);

    #pragma unroll
    for (int o = 16; o > 0; o >>= 1) {
        sa += __shfl_down_sync(0xFFFFFFFFu, sa, o);
        sk += __shfl_down_sync(0xFFFFFFFFu, sk, o);
        sv += __shfl_down_sync(0xFFFFFFFFu, sv, o);
    }

    __shared__ float wsa[8], wsk[8], wsv[8];
    if ((t & 31) == 0) {
        const int w = t >> 5;
        wsa[w] = sa; wsk[w] = sk; wsv[w] = sv;
    }
    __syncthreads();
    if (t < 8) {
        float ra = wsa[t], rk = wsk[t], rv = wsv[t];
        #pragma unroll
        for (int o = 4; o > 0; o >>= 1) {
            ra += __shfl_down_sync(0xFFu, ra, o, 8);
            rk += __shfl_down_sync(0xFFu, rk, o, 8);
            rv += __shfl_down_sync(0xFFu, rv, o, 8);
        }
        if (t == 0) {
            if (!gate) {
                g_qt[b] = ra + bq[b];
                g_k[b]  = INV_SQRT_M * (rk + bk[b]);
                g_v[b]  = rv + bV[b];
            } else {
                g_it = expf(ra + bi[0]);
                g_ft = expf(rk + bf[0]);
                float z = rv + bo[0];
                g_ot = 1.0f / (1.0f + expf(-z));
            }
        }
    }
}

// ---------------- kernel 2: sync-free cp stream + dot partials (measured 20.3us) ----------------
// One warp owns one 512-float chunk of one cp row: elementwise C write +
// warp-shuffle partial of cp@qt. No smem, no syncthreads, no ht work.
// 32768 warps = 4096 blocks x 256 threads.
__global__ __launch_bounds__(256) void cp_partial(
    const float* __restrict__ cp, float* __restrict__ outC)
{
    const int w    = blockIdx.x * 8 + (threadIdx.x >> 5);
    const int lane = threadIdx.x & 31;
    const int row  = w >> 3;
    const int ch   = w & 7;

    const float ft = g_ft;
    const float iv = g_it * g_v[row];

    const size_t base = (size_t)row * MM + ch * 512;
    const float4* P  = reinterpret_cast<const float4*>(cp + base);
    float4*       O  = reinterpret_cast<float4*>(outC + base);
    const float4* k4 = reinterpret_cast<const float4*>(g_k + ch * 512);
    const float4* q4 = reinterpret_cast<const float4*>(g_qt + ch * 512);

    // 4 independent streaming loads front-batched
    float4 c0 = __ldcs(&P[lane]);
    float4 c1 = __ldcs(&P[lane + 32]);
    float4 c2 = __ldcs(&P[lane + 64]);
    float4 c3 = __ldcs(&P[lane + 96]);
    float4 k0 = k4[lane], k1 = k4[lane + 32], k2 = k4[lane + 64], k3 = k4[lane + 96];
    float4 q0 = q4[lane], q1 = q4[lane + 32], q2 = q4[lane + 64], q3 = q4[lane + 96];

    float4 o;
    o.x = ft * c0.x + iv * k0.x; o.y = ft * c0.y + iv * k0.y;
    o.z = ft * c0.z + iv * k0.z; o.w = ft * c0.w + iv * k0.w;
    __stcs(&O[lane], o);
    o.x = ft * c1.x + iv * k1.x; o.y = ft * c1.y + iv * k1.y;
    o.z = ft * c1.z + iv * k1.z; o.w = ft * c1.w + iv * k1.w;
    __stcs(&O[lane + 32], o);
    o.x = ft * c2.x + iv * k2.x; o.y = ft * c2.y + iv * k2.y;
    o.z = ft * c2.z + iv * k2.z; o.w = ft * c2.w + iv * k2.w;
    __stcs(&O[lane + 64], o);
    o.x = ft * c3.x + iv * k3.x; o.y = ft * c3.y + iv * k3.y;
    o.z = ft * c3.z + iv * k3.z; o.w = ft * c3.w + iv * k3.w;
    __stcs(&O[lane + 96], o);

    float s = dot4(c0, q0) + dot4(c1, q1) + dot4(c2, q2) + dot4(c3, q3);
    #pragma unroll
    for (int o2 = 16; o2 > 0; o2 >>= 1) s += __shfl_down_sync(0xFFFFFFFFu, s, o2);
    if (lane == 0) g_pcp[row][ch] = s;
}

// ---------------- kernel 3: n-update + kqt/denom + ht fold ----------------
// One block, 1024 threads. Phase A: n_i = ft*n_prev_i + it*k_i, kqt = k.qt,
// denom = max(|n.qt|,1). Phase B (after one sync): fold g_pcp -> ht.
__global__ __launch_bounds__(1024) void nredh_kernel(
    const float* __restrict__ n_prev, float* __restrict__ out_n,
    float* __restrict__ outH)
{
    const int t = threadIdx.x;
    const float ft = g_ft, it = g_it;
    __shared__ float red[2][32];
    __shared__ float s_kqt, s_scale;

    // ---- phase A ----
    float kqt = 0.f, nqt = 0.f;
    #pragma unroll
    for (int u = 0; u < MM / 1024; u++) {
        const int i = t + u * 1024;
        const float k = g_k[i];
        const float q = g_qt[i];
        kqt += k * q;
        const float n = ft * n_prev[i] + it * k;
        out_n[i] = n;
        nqt += n * q;
    }
    #pragma unroll
    for (int o = 16; o > 0; o >>= 1) {
        kqt += __shfl_down_sync(0xFFFFFFFFu, kqt, o);
        nqt += __shfl_down_sync(0xFFFFFFFFu, nqt, o);
    }
    if ((t & 31) == 0) { red[0][t >> 5] = kqt; red[1][t >> 5] = nqt; }
    __syncthreads();
    if (t < 32) {
        float a = red[0][t], bb = red[1][t];
        #pragma unroll
        for (int o = 16; o > 0; o >>= 1) {
            a  += __shfl_down_sync(0xFFFFFFFFu, a, o);
            bb += __shfl_down_sync(0xFFFFFFFFu, bb, o);
        }
        if (t == 0) {
            s_kqt = a;
            s_scale = g_ot / fmaxf(fabsf(bb), 1.0f);
        }
    }
    __syncthreads();

    // ---- phase B: fold cp partials -> ht (4 rows per thread) ----
    const float kq = s_kqt;
    const float sc = s_scale;
    #pragma unroll
    for (int j = 0; j < 4; j++) {
        const int r = t + j * 1024;
        // front-batched loads
        const float4 p0 = *reinterpret_cast<const float4*>(&g_pcp[r][0]);
        const float4 p1 = *reinterpret_cast<const float4*>(&g_pcp[r][4]);
        const float vv = g_v[r];
        const float s = ((p0.x + p0.y) + (p0.z + p0.w))
                      + ((p1.x + p1.y) + (p1.z + p1.w));
        outH[r] = sc * (ft * s + it * vv * kq);
    }
}

// ---------------- launch ----------------
extern "C" void kernel_launch(void* const* d_in, const int* in_sizes, int n_in,
                              void* d_out, int out_size)
{
    const float* x      = (const float*)d_in[0];
    const float* cp     = (const float*)d_in[1];
    const float* n_prev = (const float*)d_in[2];
    const float* Wq     = (const float*)d_in[3];
    const float* bq     = (const float*)d_in[4];
    const float* Wk     = (const float*)d_in[5];
    const float* bk     = (const float*)d_in[6];
    const float* Wv     = (const float*)d_in[7];
    const float* bV     = (const float*)d_in[8];
    const float* Wi     = (const float*)d_in[9];
    const float* bi     = (const float*)d_in[10];
    const float* Wf     = (const float*)d_in[11];
    const float* bf     = (const float*)d_in[12];
    const float* Wo     = (const float*)d_in[13];
    const float* bo     = (const float*)d_in[14];

    float* out  = (float*)d_out;
    float* outH = out;                        // ht: M
    float* outC = out + MM;                   // C : M*M
    float* outN = out + MM + (size_t)MM * MM; // n : M

    mv_kernel<<<MM + 1, 256>>>(x, Wq, bq, Wk, bk, Wv, bV,
                               Wi, bi, Wf, bf, Wo, bo);
    cp_partial<<<4096, 256>>>(cp, outC);
    nredh_kernel<<<1, 1024>>>(n_prev, outN, outH);
}

// round 16
// speedup vs baseline: 1.2355x; 1.0293x over previous
#include <cuda_runtime.h>
#include <math.h>

#define MM 4096
#define DD 2048
#define INV_SQRT_M 0.015625f   // 1/sqrt(4096) exact

// ---------------- device scratch ----------------
__device__ float g_qt[MM];
__device__ float g_k[MM];
__device__ float g_v[MM];
__device__ float g_it, g_ft, g_ot;
__device__ float g_kqt, g_hscale;
__device__ float g_pcp[MM][8];      // (row, chunk) cp@qt partials

__device__ __forceinline__ float dot4(float4 a, float4 b) {
    return a.x * b.x + a.y * b.y + a.z * b.z + a.w * b.w;
}

// ---------------- kernel 1: fused q/k/v matvecs + gates (measured ~20.0us) ----------------
// grid = MM+1 blocks x 256 threads; block b < MM computes row b of Wq/Wk/Wv,
// block MM computes the three gates. 6 front-batched streaming loads/thread.
__global__ __launch_bounds__(256) void mv_kernel(
    const float* __restrict__ x,
    const float* __restrict__ Wq, const float* __restrict__ bq,
    const float* __restrict__ Wk, const float* __restrict__ bk,
    const float* __restrict__ Wv, const float* __restrict__ bV,
    const float* __restrict__ Wi, const float* __restrict__ bi,
    const float* __restrict__ Wf, const float* __restrict__ bf,
    const float* __restrict__ Wo, const float* __restrict__ bo)
{
    const int b = blockIdx.x;
    const int t = threadIdx.x;

    const bool gate = (b == MM);
    const float *rA, *rB, *rC;
    if (!gate) {
        rA = Wq + (size_t)b * DD;
        rB = Wk + (size_t)b * DD;
        rC = Wv + (size_t)b * DD;
    } else {
        rA = Wi; rB = Wf; rC = Wo;
    }

    const float4* A4 = reinterpret_cast<const float4*>(rA);
    const float4* B4 = reinterpret_cast<const float4*>(rB);
    const float4* C4 = reinterpret_cast<const float4*>(rC);
    const float4* x4 = reinterpret_cast<const float4*>(x);

    // 6 independent streaming loads, front-batched (MLP=6)
    float4 a0 = __ldcs(&A4[t]);
    float4 a1 = __ldcs(&A4[t + 256]);
    float4 k0 = __ldcs(&B4[t]);
    float4 k1 = __ldcs(&B4[t + 256]);
    float4 v0 = __ldcs(&C4[t]);
    float4 v1 = __ldcs(&C4[t + 256]);
    float4 x0 = x4[t];
    float4 x1 = x4[t + 256];

    float sa = dot4(a0, x0) + dot4(a1, x1);
    float sk = dot4(k0, x0) + dot4(k1, x1);
    float sv = dot4(v0, x0) + dot4(v1, x1);

    #pragma unroll
    for (int o = 16; o > 0; o >>= 1) {
        sa += __shfl_down_sync(0xFFFFFFFFu, sa, o);
        sk += __shfl_down_sync(0xFFFFFFFFu, sk, o);
        sv += __shfl_down_sync(0xFFFFFFFFu, sv, o);
    }

    __shared__ float wsa[8], wsk[8], wsv[8];
    if ((t & 31) == 0) {
        const int w = t >> 5;
        wsa[w] = sa; wsk[w] = sk; wsv[w] = sv;
    }
    __syncthreads();
    if (t < 8) {
        float ra = wsa[t], rk = wsk[t], rv = wsv[t];
        #pragma unroll
        for (int o = 4; o > 0; o >>= 1) {
            ra += __shfl_down_sync(0xFFu, ra, o, 8);
            rk += __shfl_down_sync(0xFFu, rk, o, 8);
            rv += __shfl_down_sync(0xFFu, rv, o, 8);
        }
        if (t == 0) {
            if (!gate) {
                g_qt[b] = ra + bq[b];
                g_k[b]  = INV_SQRT_M * (rk + bk[b]);
                g_v[b]  = rv + bV[b];
            } else {
                g_it = expf(ra + bi[0]);
                g_ft = expf(rk + bf[0]);
                float z = rv + bo[0];
                g_ot = 1.0f / (1.0f + expf(-z));
            }
        }
    }
}

// ---------------- kernel 2: scalar reductions only (1 block) ----------------
// kqt = k.qt ; npqt = n_prev.qt ; denom = max(|ft*npqt + it*kqt|, 1)
// (uses n.qt = ft*(n_prev.qt) + it*(k.qt) so n itself is not needed here)
__global__ __launch_bounds__(1024) void nred2_kernel(
    const float* __restrict__ n_prev)
{
    const int t = threadIdx.x;
    __shared__ float red[2][32];

    float kqt = 0.f, npqt = 0.f;
    #pragma unroll
    for (int u = 0; u < MM / 1024; u++) {
        const int i = t + u * 1024;
        const float q = g_qt[i];
        kqt  += g_k[i] * q;
        npqt += n_prev[i] * q;
    }
    #pragma unroll
    for (int o = 16; o > 0; o >>= 1) {
        kqt  += __shfl_down_sync(0xFFFFFFFFu, kqt, o);
        npqt += __shfl_down_sync(0xFFFFFFFFu, npqt, o);
    }
    if ((t & 31) == 0) { red[0][t >> 5] = kqt; red[1][t >> 5] = npqt; }
    __syncthreads();
    if (t < 32) {
        float a = red[0][t], bb = red[1][t];
        #pragma unroll
        for (int o = 16; o > 0; o >>= 1) {
            a  += __shfl_down_sync(0xFFFFFFFFu, a, o);
            bb += __shfl_down_sync(0xFFFFFFFFu, bb, o);
        }
        if (t == 0) {
            const float nqt = g_ft * bb + g_it * a;
            g_kqt    = a;
            g_hscale = g_ot / fmaxf(fabsf(nqt), 1.0f);
        }
    }
}

// ---------------- kernel 3: sync-free cp stream + dot partials (measured 20.3us) ----------------
// One warp owns one 512-float chunk of one cp row: elementwise C write +
// warp-shuffle partial of cp@qt. No smem, no syncthreads, no ht work.
// 32768 warps = 4096 blocks x 256 threads.
__global__ __launch_bounds__(256) void cp_partial(
    const float* __restrict__ cp, float* __restrict__ outC)
{
    const int w    = blockIdx.x * 8 + (threadIdx.x >> 5);
    const int lane = threadIdx.x & 31;
    const int row  = w >> 3;
    const int ch   = w & 7;

    const float ft = g_ft;
    const float iv = g_it * g_v[row];

    const size_t base = (size_t)row * MM + ch * 512;
    const float4* P  = reinterpret_cast<const float4*>(cp + base);
    float4*       O  = reinterpret_cast<float4*>(outC + base);
    const float4* k4 = reinterpret_cast<const float4*>(g_k + ch * 512);
    const float4* q4 = reinterpret_cast<const float4*>(g_qt + ch * 512);

    // 4 independent streaming loads front-batched
    float4 c0 = __ldcs(&P[lane]);
    float4 c1 = __ldcs(&P[lane + 32]);
    float4 c2 = __ldcs(&P[lane + 64]);
    float4 c3 = __ldcs(&P[lane + 96]);
    float4 k0 = k4[lane], k1 = k4[lane + 32], k2 = k4[lane + 64], k3 = k4[lane + 96];
    float4 q0 = q4[lane], q1 = q4[lane + 32], q2 = q4[lane + 64], q3 = q4[lane + 96];

    float4 o;
    o.x = ft * c0.x + iv * k0.x; o.y = ft * c0.y + iv * k0.y;
    o.z = ft * c0.z + iv * k0.z; o.w = ft * c0.w + iv * k0.w;
    __stcs(&O[lane], o);
    o.x = ft * c1.x + iv * k1.x; o.y = ft * c1.y + iv * k1.y;
    o.z = ft * c1.z + iv * k1.z; o.w = ft * c1.w + iv * k1.w;
    __stcs(&O[lane + 32], o);
    o.x = ft * c2.x + iv * k2.x; o.y = ft * c2.y + iv * k2.y;
    o.z = ft * c2.z + iv * k2.z; o.w = ft * c2.w + iv * k2.w;
    __stcs(&O[lane + 64], o);
    o.x = ft * c3.x + iv * k3.x; o.y = ft * c3.y + iv * k3.y;
    o.z = ft * c3.z + iv * k3.z; o.w = ft * c3.w + iv * k3.w;
    __stcs(&O[lane + 96], o);

    float s = dot4(c0, q0) + dot4(c1, q1) + dot4(c2, q2) + dot4(c3, q3);
    #pragma unroll
    for (int o2 = 16; o2 > 0; o2 >>= 1) s += __shfl_down_sync(0xFFFFFFFFu, s, o2);
    if (lane == 0) g_pcp[row][ch] = s;
}

// ---------------- kernel 4: wide elementwise tail: n-update + ht fold ----------------
// 32 blocks x 128 threads = 4096 threads, one row each, spread across SMs.
__global__ __launch_bounds__(128) void hfold_kernel(
    const float* __restrict__ n_prev,
    float* __restrict__ out_n, float* __restrict__ outH)
{
    const int r = blockIdx.x * 128 + threadIdx.x;
    const float ft = g_ft, it = g_it;

    // front-batched loads
    const float4 p0 = *reinterpret_cast<const float4*>(&g_pcp[r][0]);
    const float4 p1 = *reinterpret_cast<const float4*>(&g_pcp[r][4]);
    const float np = n_prev[r];
    const float kk = g_k[r];
    const float vv = g_v[r];

    out_n[r] = ft * np + it * kk;

    const float s = ((p0.x + p0.y) + (p0.z + p0.w))
                  + ((p1.x + p1.y) + (p1.z + p1.w));
    outH[r] = g_hscale * (ft * s + it * vv * g_kqt);
}

// ---------------- launch ----------------
extern "C" void kernel_launch(void* const* d_in, const int* in_sizes, int n_in,
                              void* d_out, int out_size)
{
    const float* x      = (const float*)d_in[0];
    const float* cp     = (const float*)d_in[1];
    const float* n_prev = (const float*)d_in[2];
    const float* Wq     = (const float*)d_in[3];
    const float* bq     = (const float*)d_in[4];
    const float* Wk     = (const float*)d_in[5];
    const float* bk     = (const float*)d_in[6];
    const float* Wv     = (const float*)d_in[7];
    const float* bV     = (const float*)d_in[8];
    const float* Wi     = (const float*)d_in[9];
    const float* bi     = (const float*)d_in[10];
    const float* Wf     = (const float*)d_in[11];
    const float* bf     = (const float*)d_in[12];
    const float* Wo     = (const float*)d_in[13];
    const float* bo     = (const float*)d_in[14];

    float* out  = (float*)d_out;
    float* outH = out;                        // ht: M
    float* outC = out + MM;                   // C : M*M
    float* outN = out + MM + (size_t)MM * MM; // n : M

    mv_kernel<<<MM + 1, 256>>>(x, Wq, bq, Wk, bk, Wv, bV,
                               Wi, bi, Wf, bf, Wo, bo);
    nred2_kernel<<<1, 1024>>>(n_prev);
    cp_partial<<<4096, 256>>>(cp, outC);
    hfold_kernel<<<32, 128>>>(n_prev, outN, outH);
}